// round 2
// baseline (speedup 1.0000x reference)
#include <cuda_runtime.h>
#include <math.h>

#define B_  4
#define L_  2048
#define IN_ 1024
#define D_  512
#define DI  1024
#define DS  128
#define HD  64
#define KC  4
#define NH  16
#define CD  1280
#define DP  2320
#define NL  2
#define NC  2
#define M_  (B_*L_)   // 8192

// ---------------- scratch (static device globals; no runtime alloc) ------------
__device__ float g_h  [M_*D_];   // residual stream
__device__ float g_u  [M_*D_];   // LN output
__device__ float g_zx [M_*DP];   // in_proj output
__device__ float g_xbc[M_*CD];   // conv+silu output
__device__ float g_dt [M_*NH];
__device__ float g_dA [M_*NH];
__device__ float g_y  [M_*DI];   // scan output / gated output

// ---------------- helpers ------------------------------------------------------
__device__ __forceinline__ float silu_f(float x) {
    return x / (1.f + __expf(-x));
}

// ---------------- GEMM: C[M,N] = A[M,K] @ W[N,K]^T (+epilogue) -----------------
// EPI: 0 = none (in_proj), 1 = +bias, exact GELU (fc1), 2 = +residual (out_proj)
template<int EPI>
__global__ __launch_bounds__(256) void gemm_k(
    const float* __restrict__ A, const float* __restrict__ W,
    const float* __restrict__ bias, const float* __restrict__ res,
    float* __restrict__ C, int M, int N, int Kd)
{
    __shared__ float As[16][128];
    __shared__ float Ws[16][128];
    const int bm = blockIdx.y * 128;
    const int bn = blockIdx.x * 128;
    const int tid = threadIdx.x;
    const int tr = tid >> 4;       // 0..15
    const int tc = tid & 15;       // 0..15

    float acc[8][8];
#pragma unroll
    for (int i = 0; i < 8; i++)
#pragma unroll
        for (int j = 0; j < 8; j++) acc[i][j] = 0.f;

    const int lrow = tid >> 1;         // 0..127
    const int lq   = (tid & 1) * 8;    // 0 or 8
    const float* Ap = A + (size_t)(bm + lrow) * Kd + lq;
    const bool  wv = (bn + lrow) < N;
    const float* Wp = W + (size_t)(wv ? (bn + lrow) : 0) * Kd + lq;

    for (int k0 = 0; k0 < Kd; k0 += 16) {
        float4 a0 = *(const float4*)(Ap + k0);
        float4 a1 = *(const float4*)(Ap + k0 + 4);
        float4 w0 = make_float4(0.f,0.f,0.f,0.f), w1 = w0;
        if (wv) { w0 = *(const float4*)(Wp + k0); w1 = *(const float4*)(Wp + k0 + 4); }
        __syncthreads();
        As[lq+0][lrow]=a0.x; As[lq+1][lrow]=a0.y; As[lq+2][lrow]=a0.z; As[lq+3][lrow]=a0.w;
        As[lq+4][lrow]=a1.x; As[lq+5][lrow]=a1.y; As[lq+6][lrow]=a1.z; As[lq+7][lrow]=a1.w;
        Ws[lq+0][lrow]=w0.x; Ws[lq+1][lrow]=w0.y; Ws[lq+2][lrow]=w0.z; Ws[lq+3][lrow]=w0.w;
        Ws[lq+4][lrow]=w1.x; Ws[lq+5][lrow]=w1.y; Ws[lq+6][lrow]=w1.z; Ws[lq+7][lrow]=w1.w;
        __syncthreads();
#pragma unroll
        for (int kk = 0; kk < 16; kk++) {
            float4 ra0 = *(const float4*)&As[kk][tr*8];
            float4 ra1 = *(const float4*)&As[kk][tr*8+4];
            float4 rw0 = *(const float4*)&Ws[kk][tc*8];
            float4 rw1 = *(const float4*)&Ws[kk][tc*8+4];
            float ra[8] = {ra0.x,ra0.y,ra0.z,ra0.w, ra1.x,ra1.y,ra1.z,ra1.w};
            float rw[8] = {rw0.x,rw0.y,rw0.z,rw0.w, rw1.x,rw1.y,rw1.z,rw1.w};
#pragma unroll
            for (int i = 0; i < 8; i++)
#pragma unroll
                for (int j = 0; j < 8; j++)
                    acc[i][j] = fmaf(ra[i], rw[j], acc[i][j]);
        }
    }

#pragma unroll
    for (int i = 0; i < 8; i++) {
        const int row = bm + tr*8 + i;
        float* Cr = C + (size_t)row * N;
#pragma unroll
        for (int j = 0; j < 8; j++) {
            const int col = bn + tc*8 + j;
            if (col < N) {
                float v = acc[i][j];
                if (EPI == 1) {
                    v += bias[col];
                    v = 0.5f * v * (1.f + erff(v * 0.70710678118654752f));
                }
                if (EPI == 2) {
                    v += res[(size_t)row * N + col];
                }
                Cr[col] = v;
            }
        }
    }
}

// ---------------- LayerNorm over last dim (512) --------------------------------
__global__ __launch_bounds__(256) void ln_k(
    const float* __restrict__ x, const float* __restrict__ w,
    const float* __restrict__ b, float* __restrict__ o)
{
    __shared__ float red[256];
    const int row = blockIdx.x;
    const int tid = threadIdx.x;
    const float* xr = x + (size_t)row * D_;
    float v0 = xr[tid], v1 = xr[tid + 256];

    red[tid] = v0 + v1;
    __syncthreads();
    for (int st = 128; st > 0; st >>= 1) {
        if (tid < st) red[tid] += red[tid + st];
        __syncthreads();
    }
    const float mean = red[0] * (1.f / D_);
    __syncthreads();
    const float d0 = v0 - mean, d1 = v1 - mean;
    red[tid] = d0*d0 + d1*d1;
    __syncthreads();
    for (int st = 128; st > 0; st >>= 1) {
        if (tid < st) red[tid] += red[tid + st];
        __syncthreads();
    }
    const float rstd = rsqrtf(red[0] * (1.f / D_) + 1e-5f);
    float* orow = o + (size_t)row * D_;
    orow[tid]       = d0 * rstd * w[tid]       + b[tid];
    orow[tid + 256] = d1 * rstd * w[tid + 256] + b[tid + 256];
}

// ---------------- causal depthwise conv (K=4) + SiLU ---------------------------
__global__ void conv_k(const float* __restrict__ zx, const float* __restrict__ w,
                       const float* __restrict__ bias, float* __restrict__ out)
{
    const int idx = blockIdx.x * blockDim.x + threadIdx.x;
    if (idx >= M_ * CD) return;
    const int c = idx % CD;
    const int m = idx / CD;    // b*L + t
    const int t = m % L_;
    float acc = bias[c];
#pragma unroll
    for (int k = 0; k < KC; k++) {
        const int tt = t + k - (KC - 1);
        if (tt >= 0)
            acc = fmaf(zx[(size_t)(m + k - (KC-1)) * DP + DI + c], w[c*KC + k], acc);
    }
    out[idx] = silu_f(acc);
}

// ---------------- dt = softplus(dt+bias); dA = exp(dt * -exp(A_log)) -----------
__global__ void dt_k(const float* __restrict__ zx, const float* __restrict__ dtb,
                     const float* __restrict__ Alog,
                     float* __restrict__ dt, float* __restrict__ dA)
{
    const int idx = blockIdx.x * blockDim.x + threadIdx.x;
    if (idx >= M_ * NH) return;
    const int hh = idx % NH;
    const int m  = idx / NH;
    const float v = zx[(size_t)m * DP + DI + CD + hh] + dtb[hh];
    const float sp = (v > 20.f) ? v : log1pf(expf(v));
    dt[idx] = sp;
    dA[idx] = expf(sp * -expf(Alog[hh]));
}

// ---------------- sequential SSM scan ------------------------------------------
// grid: (2 p-splits, NH, B). block 256 = 32 p-lanes x 8 n-groups (16 n each).
// Each thread holds 16 state elements h[p, n0..n0+15] in registers.
__global__ __launch_bounds__(256) void scan_k(
    const float* __restrict__ xbc, const float* __restrict__ dt,
    const float* __restrict__ dA, const float* __restrict__ Dp,
    float* __restrict__ y)
{
    __shared__ float shB[DS], shC[DS], shX[32], red[256];
    const int psplit = blockIdx.x;
    const int h  = blockIdx.y;
    const int b  = blockIdx.z;
    const int tid = threadIdx.x;
    const int plocal = tid & 31;
    const int ngrp = tid >> 5;
    const int n0 = ngrp * 16;
    const int pg = psplit * 32 + plocal;
    const float Dv = Dp[h];

    float s[16];
#pragma unroll
    for (int j = 0; j < 16; j++) s[j] = 0.f;

    const size_t base = (size_t)b * L_;
    // preload t = 0
    float rB = 0.f, rC = 0.f, rX = 0.f;
    {
        const float* p = xbc + base * CD;
        if (tid < DS) rB = p[DI + tid];
        else          rC = p[DI + DS + (tid - DS)];
        if (tid < 32) rX = p[h*HD + pg];
    }

    for (int t = 0; t < L_; t++) {
        __syncthreads();
        if (tid < DS) shB[tid] = rB; else shC[tid - DS] = rC;
        if (tid < 32) shX[tid] = rX;
        // prefetch t+1 while this step computes
        if (t + 1 < L_) {
            const float* p = xbc + (base + t + 1) * CD;
            if (tid < DS) rB = p[DI + tid];
            else          rC = p[DI + DS + (tid - DS)];
            if (tid < 32) rX = p[h*HD + pg];
        }
        const float dAv = dA[(base + t)*NH + h];
        const float dtv = dt[(base + t)*NH + h];
        __syncthreads();

        const float a = dtv * shX[plocal];
        float part = 0.f;
#pragma unroll
        for (int j = 0; j < 16; j++) {
            s[j] = fmaf(s[j], dAv, a * shB[n0 + j]);
            part = fmaf(s[j], shC[n0 + j], part);
        }
        red[ngrp*32 + plocal] = part;
        __syncthreads();
        if (tid < 32) {
            float acc = shX[tid] * Dv;
#pragma unroll
            for (int g2 = 0; g2 < 8; g2++) acc += red[g2*32 + tid];
            y[(base + t)*DI + h*HD + pg] = acc;
        }
    }
}

// ---------------- gating (y * silu(z)) + RMSNorm * gnorm_w ---------------------
__global__ __launch_bounds__(256) void gate_k(
    const float* __restrict__ zx, const float* __restrict__ gw,
    float* __restrict__ y)
{
    __shared__ float red[256];
    const int row = blockIdx.x;
    const int tid = threadIdx.x;
    const float* zr = zx + (size_t)row * DP;
    float* yr = y + (size_t)row * DI;
    float g[4]; float ss = 0.f;
#pragma unroll
    for (int i = 0; i < 4; i++) {
        const int c = tid + i*256;
        const float z = zr[c];
        const float gv = yr[c] * silu_f(z);
        g[i] = gv; ss += gv * gv;
    }
    red[tid] = ss;
    __syncthreads();
    for (int st = 128; st > 0; st >>= 1) {
        if (tid < st) red[tid] += red[tid + st];
        __syncthreads();
    }
    const float scale = rsqrtf(red[0] * (1.f / DI) + 1e-5f);
#pragma unroll
    for (int i = 0; i < 4; i++) {
        const int c = tid + i*256;
        yr[c] = g[i] * scale * gw[c];
    }
}

// ---------------- classifier: out[m, c] = h[m,:] . cls_w[c,:] + cls_b[c] -------
__global__ void cls_k(const float* __restrict__ h, const float* __restrict__ w,
                      const float* __restrict__ b, float* __restrict__ out)
{
    const int gwarp = (blockIdx.x * blockDim.x + threadIdx.x) >> 5;
    const int lane = threadIdx.x & 31;
    if (gwarp >= M_) return;
    const float* hr = h + (size_t)gwarp * D_;
    float a0 = 0.f, a1 = 0.f;
    for (int k = lane; k < D_; k += 32) {
        const float hv = hr[k];
        a0 = fmaf(hv, w[k],      a0);
        a1 = fmaf(hv, w[D_ + k], a1);
    }
    for (int off = 16; off; off >>= 1) {
        a0 += __shfl_xor_sync(0xFFFFFFFFu, a0, off);
        a1 += __shfl_xor_sync(0xFFFFFFFFu, a1, off);
    }
    if (lane == 0) {
        out[gwarp*2 + 0] = a0 + b[0];
        out[gwarp*2 + 1] = a1 + b[1];
    }
}

// ---------------- launch -------------------------------------------------------
extern "C" void kernel_launch(void* const* d_in, const int* in_sizes, int n_in,
                              void* d_out, int out_size)
{
    const float* x      = (const float*)d_in[0];
    const float* fc1_w  = (const float*)d_in[1];
    const float* fc1_b  = (const float*)d_in[2];
    const float* ln_w   = (const float*)d_in[3];
    const float* ln_b   = (const float*)d_in[4];
    const float* in_w   = (const float*)d_in[5];
    const float* conv_w = (const float*)d_in[6];
    const float* conv_b = (const float*)d_in[7];
    const float* dt_b   = (const float*)d_in[8];
    const float* A_log  = (const float*)d_in[9];
    const float* D_p    = (const float*)d_in[10];
    const float* gn_w   = (const float*)d_in[11];
    const float* out_w  = (const float*)d_in[12];
    const float* cls_w  = (const float*)d_in[13];
    const float* cls_b  = (const float*)d_in[14];
    float* out = (float*)d_out;

    float *h, *u, *zx, *xbc, *dtp, *dAp, *y;
    cudaGetSymbolAddress((void**)&h,   g_h);
    cudaGetSymbolAddress((void**)&u,   g_u);
    cudaGetSymbolAddress((void**)&zx,  g_zx);
    cudaGetSymbolAddress((void**)&xbc, g_xbc);
    cudaGetSymbolAddress((void**)&dtp, g_dt);
    cudaGetSymbolAddress((void**)&dAp, g_dA);
    cudaGetSymbolAddress((void**)&y,   g_y);

    // fc1 + GELU: h = gelu(x @ fc1_w^T + b)
    gemm_k<1><<<dim3(D_/128, M_/128), 256>>>(x, fc1_w, fc1_b, nullptr, h, M_, D_, IN_);

    for (int l = 0; l < NL; l++) {
        ln_k<<<M_, 256>>>(h, ln_w + l*D_, ln_b + l*D_, u);
        gemm_k<0><<<dim3((DP + 127)/128, M_/128), 256>>>(
            u, in_w + (size_t)l*DP*D_, nullptr, nullptr, zx, M_, DP, D_);
        conv_k<<<(M_*CD + 255)/256, 256>>>(zx, conv_w + l*CD*KC, conv_b + l*CD, xbc);
        dt_k<<<(M_*NH + 255)/256, 256>>>(zx, dt_b + l*NH, A_log + l*NH, dtp, dAp);
        scan_k<<<dim3(2, NH, B_), 256>>>(xbc, dtp, dAp, D_p + l*NH, y);
        gate_k<<<M_, 256>>>(zx, gn_w + l*DI, y);
        gemm_k<2><<<dim3(D_/128, M_/128), 256>>>(
            y, out_w + (size_t)l*D_*DI, nullptr, h, h, M_, D_, DI);
    }

    cls_k<<<(M_*32 + 255)/256, 256>>>(h, cls_w, cls_b, out);
}